// round 2
// baseline (speedup 1.0000x reference)
#include <cuda_runtime.h>
#include <cuda_bf16.h>
#include <cstdint>

// N=100000 nodes, D=256 features, E=3200000 edges.
#define MAX_N 100000
#define MAX_E 3200000
#define FEAT_D 256

__device__ float g_diag[MAX_N];   // sigmoid(x @ w + b)
__device__ float g_deg[MAX_N];    // degree over col
__device__ int   g_is64;          // 1 if edge_index is int64
// scratch int32 indices, used only when output is values-only (non-mode3)
__device__ int   g_r32[MAX_E];
__device__ int   g_c32[MAX_E];

// ---------------------------------------------------------------------------
// K0: zero g_deg + probe index width (block 0, warp 0).
// int64 values < 2^32 have all-zero odd 32-bit words.
// ---------------------------------------------------------------------------
__global__ void zero_probe_kernel(const int* __restrict__ ei_words, int n) {
    if (blockIdx.x == 0 && threadIdx.x < 32) {
        int nz = 0;
        for (int i = threadIdx.x; i < 256; i += 32)
            if (ei_words[2 * i + 1] != 0) nz++;
        #pragma unroll
        for (int o = 16; o; o >>= 1) nz += __shfl_xor_sync(0xFFFFFFFFu, nz, o);
        if (threadIdx.x == 0) g_is64 = (nz == 0) ? 1 : 0;
    }
    int base = (blockIdx.x * blockDim.x + threadIdx.x) * 4;
    #pragma unroll
    for (int k = 0; k < 4; k++)
        if (base + k < n) g_deg[base + k] = 0.0f;
}

// ---------------------------------------------------------------------------
// K1 fused: diag blocks (4 of every 5) + edge blocks (1 of every 5).
// Diag block: 8 rows, one warp per row (coalesced 1KB row read, DRAM-bound).
// Edge block: 1024 edges: read int64/int32 indices, deg atomics (L2-bound),
//             convert indices to float and write them to out (mode3) or
//             int32 scratch (values-only mode). These two block types are
//             bottlenecked on different resources -> interleave for overlap.
// ---------------------------------------------------------------------------
__global__ void fused_kernel(const float* __restrict__ x,
                             const float* __restrict__ w,
                             const float* __restrict__ b,
                             const void* __restrict__ eidx,
                             float* __restrict__ out,
                             int n, int E, int mode3) {
    int role = blockIdx.x % 5;   // 0..3: diag, 4: edge
    if (role != 4) {
        // ---- diag part ----
        int db = (blockIdx.x / 5) * 4 + role;      // dense diag-block id
        int warp = (db * 8) + (threadIdx.x >> 5);
        int lane = threadIdx.x & 31;
        if (warp >= n) return;

        const float4* xr = reinterpret_cast<const float4*>(x + (size_t)warp * FEAT_D);
        const float4* w4 = reinterpret_cast<const float4*>(w);

        float4 a0 = xr[lane];
        float4 a1 = xr[lane + 32];
        float4 w0 = __ldg(&w4[lane]);
        float4 w1 = __ldg(&w4[lane + 32]);

        float s = a0.x * w0.x + a0.y * w0.y + a0.z * w0.z + a0.w * w0.w
                + a1.x * w1.x + a1.y * w1.y + a1.z * w1.z + a1.w * w1.w;
        #pragma unroll
        for (int o = 16; o; o >>= 1) s += __shfl_xor_sync(0xFFFFFFFFu, s, o);

        if (lane == 0) {
            float z = s + __ldg(b);
            g_diag[warp] = 1.0f / (1.0f + expf(-z));
        }
    } else {
        // ---- edge part: 1024 edges per block ----
        int eb = blockIdx.x / 5;
        int blockbase = eb * 1024;
        int tid = threadIdx.x;
        bool is64 = (g_is64 != 0);

        #pragma unroll
        for (int i = 0; i < 2; i++) {
            int idx = blockbase + i * 512 + tid * 2;   // 2 edges per thread
            if (idx + 1 < E) {
                int r0, r1, c0, c1;
                if (is64) {
                    const longlong2* R = reinterpret_cast<const longlong2*>(
                        reinterpret_cast<const long long*>(eidx) + idx);
                    const longlong2* C = reinterpret_cast<const longlong2*>(
                        reinterpret_cast<const long long*>(eidx) + (size_t)E + idx);
                    longlong2 rv = *R; longlong2 cv = *C;
                    r0 = (int)rv.x; r1 = (int)rv.y;
                    c0 = (int)cv.x; c1 = (int)cv.y;
                } else {
                    const int2* R = reinterpret_cast<const int2*>(
                        reinterpret_cast<const int*>(eidx) + idx);
                    const int2* C = reinterpret_cast<const int2*>(
                        reinterpret_cast<const int*>(eidx) + (size_t)E + idx);
                    int2 rv = *R; int2 cv = *C;
                    r0 = rv.x; r1 = rv.y; c0 = cv.x; c1 = cv.y;
                }
                atomicAdd(&g_deg[c0], 1.0f);
                atomicAdd(&g_deg[c1], 1.0f);
                if (mode3) {
                    *reinterpret_cast<float2*>(out + idx) =
                        make_float2((float)r0, (float)r1);
                    *reinterpret_cast<float2*>(out + (size_t)E + idx) =
                        make_float2((float)c0, (float)c1);
                } else {
                    *reinterpret_cast<int2*>(g_r32 + idx) = make_int2(r0, r1);
                    *reinterpret_cast<int2*>(g_c32 + idx) = make_int2(c0, c1);
                }
            } else {
                for (int e = idx; e < E; e++) {
                    int r, c;
                    if (is64) {
                        r = (int)reinterpret_cast<const long long*>(eidx)[e];
                        c = (int)reinterpret_cast<const long long*>(eidx)[(size_t)E + e];
                    } else {
                        r = reinterpret_cast<const int*>(eidx)[e];
                        c = reinterpret_cast<const int*>(eidx)[(size_t)E + e];
                    }
                    atomicAdd(&g_deg[c], 1.0f);
                    if (mode3) { out[e] = (float)r; out[(size_t)E + e] = (float)c; }
                    else       { g_r32[e] = r; g_c32[e] = c; }
                }
            }
        }
    }
}

// ---------------------------------------------------------------------------
// K2: vals[e] = (1/deg[row]) * attr[e] * diag[col].
// mode3: indices already in out[0..2E) as exact floats -> read 4B coalesced.
// ---------------------------------------------------------------------------
__global__ void val_kernel(const float* __restrict__ attr,
                           float* __restrict__ out,
                           int E, int mode3) {
    int base = (blockIdx.x * blockDim.x + threadIdx.x) * 4;
    if (base >= E) return;
    bool full = (base + 3 < E);

    int r[4], c[4];
    if (mode3) {
        if (full) {
            float4 rf = *reinterpret_cast<const float4*>(out + base);
            float4 cf = *reinterpret_cast<const float4*>(out + (size_t)E + base);
            r[0] = (int)rf.x; r[1] = (int)rf.y; r[2] = (int)rf.z; r[3] = (int)rf.w;
            c[0] = (int)cf.x; c[1] = (int)cf.y; c[2] = (int)cf.z; c[3] = (int)cf.w;
        } else {
            #pragma unroll
            for (int k = 0; k < 4; k++) {
                int e = min(base + k, E - 1);
                r[k] = (int)out[e]; c[k] = (int)out[(size_t)E + e];
            }
        }
    } else {
        if (full) {
            int4 ri = *reinterpret_cast<const int4*>(g_r32 + base);
            int4 ci = *reinterpret_cast<const int4*>(g_c32 + base);
            r[0] = ri.x; r[1] = ri.y; r[2] = ri.z; r[3] = ri.w;
            c[0] = ci.x; c[1] = ci.y; c[2] = ci.z; c[3] = ci.w;
        } else {
            #pragma unroll
            for (int k = 0; k < 4; k++) {
                int e = min(base + k, E - 1);
                r[k] = g_r32[e]; c[k] = g_c32[e];
            }
        }
    }

    float a[4];
    if (full) {
        float4 av = *reinterpret_cast<const float4*>(attr + base);
        a[0] = av.x; a[1] = av.y; a[2] = av.z; a[3] = av.w;
    } else {
        #pragma unroll
        for (int k = 0; k < 4; k++) a[k] = attr[min(base + k, E - 1)];
    }

    float v[4];
    #pragma unroll
    for (int k = 0; k < 4; k++) {
        float dinv = 1.0f / __ldg(&g_deg[r[k]]);
        v[k] = dinv * a[k] * __ldg(&g_diag[c[k]]);
    }

    float* vo = mode3 ? (out + (size_t)2 * E) : out;
    if (full) {
        *reinterpret_cast<float4*>(vo + base) = make_float4(v[0], v[1], v[2], v[3]);
    } else {
        for (int e = base; e < E; e++) vo[e] = v[e - base];
    }
}

// ---------------------------------------------------------------------------
// Launch. Inputs: x [N*D] f32, edge_index [2*E] int, edge_attr [E] f32,
// w [D] f32, b [1] f32.
// ---------------------------------------------------------------------------
extern "C" void kernel_launch(void* const* d_in, const int* in_sizes, int n_in,
                              void* d_out, int out_size) {
    const float* x    = (const float*)d_in[0];
    const void*  ei   = d_in[1];
    const float* attr = (const float*)d_in[2];
    const float* w    = (const float*)d_in[3];
    const float* b    = (const float*)d_in[4];
    float* out = (float*)d_out;

    int E = in_sizes[2];
    int N = in_sizes[0] / FEAT_D;
    int mode3 = (out_size >= 3 * E) ? 1 : 0;

    // K0: zero degrees + probe index width
    int zblocks = (N + 1023) / 1024;
    zero_probe_kernel<<<zblocks, 256>>>((const int*)ei, N);

    // K1: fused diag + deg + index conversion.
    // diag needs ceil(N/8) warp-groups; edge needs ceil(E/1024) blocks.
    // Grid interleaves them 4:1 (roles 0-3 diag, role 4 edge).
    int diag_blocks = (N + 7) / 8;              // 12500
    int edge_blocks = (E + 1023) / 1024;        // 3125
    int grid = max(((diag_blocks + 3) / 4) * 5, edge_blocks * 5);
    fused_kernel<<<grid, 256>>>(x, w, b, ei, out, N, E, mode3);

    // K2: values
    int vthreads = (E + 3) / 4;
    int vblocks  = (vthreads + 255) / 256;
    val_kernel<<<vblocks, 256>>>(attr, out, E, mode3);
}

// round 3
// speedup vs baseline: 1.1844x; 1.1844x over previous
#include <cuda_runtime.h>
#include <cuda_bf16.h>
#include <cstdint>

// N=100000 nodes, D=256 features, E=3200000 edges.
#define MAX_N 100000
#define MAX_E 3200000
#define FEAT_D 256

__device__ float g_diag[MAX_N];   // sigmoid(x @ w + b)
__device__ float g_deg[MAX_N];    // degree over col, then 1/deg after recip pass
// scratch int32 indices, used only when output is values-only (non-mode3)
__device__ int   g_r32[MAX_E];
__device__ int   g_c32[MAX_E];

// ---------------------------------------------------------------------------
// Local is64 detection: int64 little-endian values < 2^32 have zero odd words.
// 8 samples; for int32 inputs the odd words are node indices, all-zero w.p.
// ~1e-40. One thread per block, L2-hit after the first block.
// ---------------------------------------------------------------------------
__device__ __forceinline__ int detect_is64(const void* eidx) {
    const int* wds = reinterpret_cast<const int*>(eidx);
    int nz = 0;
    #pragma unroll
    for (int i = 0; i < 8; i++) nz |= wds[2 * i + 1];
    return nz == 0;
}

// ---------------------------------------------------------------------------
// K1: diag[i] = sigmoid(dot(x[i,:], w) + b); also zero g_deg.
// One warp per row; each lane loads 2 float4 of x; w is L1-resident.
// Pure DRAM-streaming (102.4 MB).
// ---------------------------------------------------------------------------
__global__ void diag_kernel(const float* __restrict__ x,
                            const float* __restrict__ w,
                            const float* __restrict__ b,
                            int n) {
    int gtid = blockIdx.x * blockDim.x + threadIdx.x;
    if (gtid < n) g_deg[gtid] = 0.0f;

    int warp = gtid >> 5;
    int lane = threadIdx.x & 31;
    if (warp >= n) return;

    const float4* xr = reinterpret_cast<const float4*>(x + (size_t)warp * FEAT_D);
    const float4* w4 = reinterpret_cast<const float4*>(w);

    float4 a0 = xr[lane];
    float4 a1 = xr[lane + 32];
    float4 w0 = __ldg(&w4[lane]);
    float4 w1 = __ldg(&w4[lane + 32]);

    float s = a0.x * w0.x + a0.y * w0.y + a0.z * w0.z + a0.w * w0.w
            + a1.x * w1.x + a1.y * w1.y + a1.z * w1.z + a1.w * w1.w;
    #pragma unroll
    for (int o = 16; o; o >>= 1) s += __shfl_xor_sync(0xFFFFFFFFu, s, o);

    if (lane == 0) {
        float z = s + __ldg(b);
        g_diag[warp] = 1.0f / (1.0f + expf(-z));
    }
}

// ---------------------------------------------------------------------------
// K2: degree atomics over col + index conversion. 4 edges per thread.
// Reads int64 (or int32) indices ONCE; writes float indices to out (mode3)
// or int32 scratch (values-only), so val_kernel never touches int64 again.
// ---------------------------------------------------------------------------
__global__ void deg_conv_kernel(const void* __restrict__ eidx,
                                float* __restrict__ out,
                                int E, int mode3) {
    __shared__ int s_is64;
    if (threadIdx.x == 0) s_is64 = detect_is64(eidx);
    __syncthreads();
    bool is64 = (s_is64 != 0);

    int base = (blockIdx.x * blockDim.x + threadIdx.x) * 4;
    if (base >= E) return;

    int r[4], c[4];
    if (base + 3 < E) {
        if (is64) {
            const long long* R = reinterpret_cast<const long long*>(eidx);
            const long long* C = R + E;
            longlong2 r01 = *reinterpret_cast<const longlong2*>(R + base);
            longlong2 r23 = *reinterpret_cast<const longlong2*>(R + base + 2);
            longlong2 c01 = *reinterpret_cast<const longlong2*>(C + base);
            longlong2 c23 = *reinterpret_cast<const longlong2*>(C + base + 2);
            r[0] = (int)r01.x; r[1] = (int)r01.y; r[2] = (int)r23.x; r[3] = (int)r23.y;
            c[0] = (int)c01.x; c[1] = (int)c01.y; c[2] = (int)c23.x; c[3] = (int)c23.y;
        } else {
            const int* R = reinterpret_cast<const int*>(eidx);
            const int* C = R + E;
            int4 ri = *reinterpret_cast<const int4*>(R + base);
            int4 ci = *reinterpret_cast<const int4*>(C + base);
            r[0] = ri.x; r[1] = ri.y; r[2] = ri.z; r[3] = ri.w;
            c[0] = ci.x; c[1] = ci.y; c[2] = ci.z; c[3] = ci.w;
        }
        #pragma unroll
        for (int k = 0; k < 4; k++) atomicAdd(&g_deg[c[k]], 1.0f);
        if (mode3) {
            *reinterpret_cast<float4*>(out + base) =
                make_float4((float)r[0], (float)r[1], (float)r[2], (float)r[3]);
            *reinterpret_cast<float4*>(out + (size_t)E + base) =
                make_float4((float)c[0], (float)c[1], (float)c[2], (float)c[3]);
        } else {
            *reinterpret_cast<int4*>(g_r32 + base) = make_int4(r[0], r[1], r[2], r[3]);
            *reinterpret_cast<int4*>(g_c32 + base) = make_int4(c[0], c[1], c[2], c[3]);
        }
    } else {
        for (int e = base; e < E; e++) {
            int rr, cc;
            if (is64) {
                rr = (int)reinterpret_cast<const long long*>(eidx)[e];
                cc = (int)reinterpret_cast<const long long*>(eidx)[(size_t)E + e];
            } else {
                rr = reinterpret_cast<const int*>(eidx)[e];
                cc = reinterpret_cast<const int*>(eidx)[(size_t)E + e];
            }
            atomicAdd(&g_deg[cc], 1.0f);
            if (mode3) { out[e] = (float)rr; out[(size_t)E + e] = (float)cc; }
            else       { g_r32[e] = rr; g_c32[e] = cc; }
        }
    }
}

// ---------------------------------------------------------------------------
// K3: g_deg[i] = 1/g_deg[i]. Hoists 3.2M per-edge RCPs down to 100k.
// (Zero-degree nodes -> inf, matching deg^-1 semantics.)
// ---------------------------------------------------------------------------
__global__ void recip_kernel(int n) {
    int i = blockIdx.x * blockDim.x + threadIdx.x;
    if (i < n) g_deg[i] = 1.0f / g_deg[i];
}

// ---------------------------------------------------------------------------
// K4: vals[e] = deginv[row] * attr[e] * diag[col]. 8 edges per thread for MLP.
// Indices re-read as coalesced 4B floats (mode3) / int32 scratch.
// ---------------------------------------------------------------------------
__global__ void val_kernel(const float* __restrict__ attr,
                           float* __restrict__ out,
                           int E, int mode3) {
    int base = (blockIdx.x * blockDim.x + threadIdx.x) * 8;
    if (base >= E) return;
    float* vo = mode3 ? (out + (size_t)2 * E) : out;

    if (base + 7 < E) {
        int r[8], c[8];
        if (mode3) {
            const float4* RF = reinterpret_cast<const float4*>(out + base);
            const float4* CF = reinterpret_cast<const float4*>(out + (size_t)E + base);
            float4 r0 = RF[0], r1 = RF[1];
            float4 c0 = CF[0], c1 = CF[1];
            r[0]=(int)r0.x; r[1]=(int)r0.y; r[2]=(int)r0.z; r[3]=(int)r0.w;
            r[4]=(int)r1.x; r[5]=(int)r1.y; r[6]=(int)r1.z; r[7]=(int)r1.w;
            c[0]=(int)c0.x; c[1]=(int)c0.y; c[2]=(int)c0.z; c[3]=(int)c0.w;
            c[4]=(int)c1.x; c[5]=(int)c1.y; c[6]=(int)c1.z; c[7]=(int)c1.w;
        } else {
            const int4* RI = reinterpret_cast<const int4*>(g_r32 + base);
            const int4* CI = reinterpret_cast<const int4*>(g_c32 + base);
            int4 r0 = RI[0], r1 = RI[1];
            int4 c0 = CI[0], c1 = CI[1];
            r[0]=r0.x; r[1]=r0.y; r[2]=r0.z; r[3]=r0.w;
            r[4]=r1.x; r[5]=r1.y; r[6]=r1.z; r[7]=r1.w;
            c[0]=c0.x; c[1]=c0.y; c[2]=c0.z; c[3]=c0.w;
            c[4]=c1.x; c[5]=c1.y; c[6]=c1.z; c[7]=c1.w;
        }

        const float4* AF = reinterpret_cast<const float4*>(attr + base);
        float4 a0 = AF[0], a1 = AF[1];
        float a[8] = {a0.x, a0.y, a0.z, a0.w, a1.x, a1.y, a1.z, a1.w};

        // issue all 16 gathers back-to-back for maximum MLP
        float di[8], dg[8];
        #pragma unroll
        for (int k = 0; k < 8; k++) di[k] = __ldg(&g_deg[r[k]]);
        #pragma unroll
        for (int k = 0; k < 8; k++) dg[k] = __ldg(&g_diag[c[k]]);

        float v[8];
        #pragma unroll
        for (int k = 0; k < 8; k++) v[k] = di[k] * a[k] * dg[k];

        *reinterpret_cast<float4*>(vo + base) =
            make_float4(v[0], v[1], v[2], v[3]);
        *reinterpret_cast<float4*>(vo + base + 4) =
            make_float4(v[4], v[5], v[6], v[7]);
    } else {
        for (int e = base; e < E; e++) {
            int rr = mode3 ? (int)out[e] : g_r32[e];
            int cc = mode3 ? (int)out[(size_t)E + e] : g_c32[e];
            vo[e] = __ldg(&g_deg[rr]) * attr[e] * __ldg(&g_diag[cc]);
        }
    }
}

// ---------------------------------------------------------------------------
// Launch. Inputs: x [N*D] f32, edge_index [2*E] int, edge_attr [E] f32,
// w [D] f32, b [1] f32.
// ---------------------------------------------------------------------------
extern "C" void kernel_launch(void* const* d_in, const int* in_sizes, int n_in,
                              void* d_out, int out_size) {
    const float* x    = (const float*)d_in[0];
    const void*  ei   = d_in[1];
    const float* attr = (const float*)d_in[2];
    const float* w    = (const float*)d_in[3];
    const float* b    = (const float*)d_in[4];
    float* out = (float*)d_out;

    int E = in_sizes[2];
    int N = in_sizes[0] / FEAT_D;
    int mode3 = (out_size >= 3 * E) ? 1 : 0;

    // K1: diag + zero deg (one warp per node, 8 warps per block)
    int diag_blocks = (N + 7) / 8;
    diag_kernel<<<diag_blocks, 256>>>(x, w, b, N);

    // K2: degree atomics + index conversion (4 edges/thread)
    int dthreads = (E + 3) / 4;
    int dblocks  = (dthreads + 255) / 256;
    deg_conv_kernel<<<dblocks, 256>>>(ei, out, E, mode3);

    // K3: deg -> 1/deg
    recip_kernel<<<(N + 255) / 256, 256>>>(N);

    // K4: values (8 edges/thread)
    int vthreads = (E + 7) / 8;
    int vblocks  = (vthreads + 255) / 256;
    val_kernel<<<vblocks, 256>>>(attr, out, E, mode3);
}

// round 4
// speedup vs baseline: 1.2367x; 1.0442x over previous
#include <cuda_runtime.h>
#include <cuda_bf16.h>
#include <cstdint>

// N=100000 nodes, D=256 features, E=3200000 edges.
#define MAX_N 100000
#define MAX_E 3200000
#define FEAT_D 256

__device__ float g_diag[MAX_N];   // sigmoid(x @ w + b)
__device__ float g_deg[MAX_N];    // degree over col (raw counts)
// scratch int32 indices, used only when output is values-only (non-mode3)
__device__ int   g_r32[MAX_E];
__device__ int   g_c32[MAX_E];

// ---------------------------------------------------------------------------
// Local is64 detection: int64 little-endian values < 2^32 have zero odd words.
// ---------------------------------------------------------------------------
__device__ __forceinline__ int detect_is64(const void* eidx) {
    const int* wds = reinterpret_cast<const int*>(eidx);
    int nz = 0;
    #pragma unroll
    for (int i = 0; i < 8; i++) nz |= wds[2 * i + 1];
    return nz == 0;
}

// ---------------------------------------------------------------------------
// K-A: diag[i] = sigmoid(dot(x[i,:], w) + b).
// One warp per row; pure DRAM streaming of x (102.4 MB).
// ---------------------------------------------------------------------------
__global__ void diag_kernel(const float* __restrict__ x,
                            const float* __restrict__ w,
                            const float* __restrict__ b,
                            int n) {
    int warp = (blockIdx.x * blockDim.x + threadIdx.x) >> 5;
    int lane = threadIdx.x & 31;
    if (warp >= n) return;

    const float4* xr = reinterpret_cast<const float4*>(x + (size_t)warp * FEAT_D);
    const float4* w4 = reinterpret_cast<const float4*>(w);

    float4 a0 = xr[lane];
    float4 a1 = xr[lane + 32];
    float4 w0 = __ldg(&w4[lane]);
    float4 w1 = __ldg(&w4[lane + 32]);

    float s = a0.x * w0.x + a0.y * w0.y + a0.z * w0.z + a0.w * w0.w
            + a1.x * w1.x + a1.y * w1.y + a1.z * w1.z + a1.w * w1.w;
    #pragma unroll
    for (int o = 16; o; o >>= 1) s += __shfl_xor_sync(0xFFFFFFFFu, s, o);

    if (lane == 0) {
        float z = s + __ldg(b);
        g_diag[warp] = 1.0f / (1.0f + expf(-z));
    }
}

// ---------------------------------------------------------------------------
// K-B: degree atomics over col + index conversion. 4 edges per thread.
// Reads int64/int32 indices ONCE; writes float indices to out (mode3) or
// int32 scratch so val_kernel never touches int64 again.
// ---------------------------------------------------------------------------
__global__ void deg_conv_kernel(const void* __restrict__ eidx,
                                float* __restrict__ out,
                                int E, int mode3) {
    __shared__ int s_is64;
    if (threadIdx.x == 0) s_is64 = detect_is64(eidx);
    __syncthreads();
    bool is64 = (s_is64 != 0);

    int base = (blockIdx.x * blockDim.x + threadIdx.x) * 4;
    if (base >= E) return;

    int r[4], c[4];
    if (base + 3 < E) {
        if (is64) {
            const long long* R = reinterpret_cast<const long long*>(eidx);
            const long long* C = R + E;
            longlong2 r01 = *reinterpret_cast<const longlong2*>(R + base);
            longlong2 r23 = *reinterpret_cast<const longlong2*>(R + base + 2);
            longlong2 c01 = *reinterpret_cast<const longlong2*>(C + base);
            longlong2 c23 = *reinterpret_cast<const longlong2*>(C + base + 2);
            r[0] = (int)r01.x; r[1] = (int)r01.y; r[2] = (int)r23.x; r[3] = (int)r23.y;
            c[0] = (int)c01.x; c[1] = (int)c01.y; c[2] = (int)c23.x; c[3] = (int)c23.y;
        } else {
            const int* R = reinterpret_cast<const int*>(eidx);
            const int* C = R + E;
            int4 ri = *reinterpret_cast<const int4*>(R + base);
            int4 ci = *reinterpret_cast<const int4*>(C + base);
            r[0] = ri.x; r[1] = ri.y; r[2] = ri.z; r[3] = ri.w;
            c[0] = ci.x; c[1] = ci.y; c[2] = ci.z; c[3] = ci.w;
        }
        #pragma unroll
        for (int k = 0; k < 4; k++) atomicAdd(&g_deg[c[k]], 1.0f);
        if (mode3) {
            *reinterpret_cast<float4*>(out + base) =
                make_float4((float)r[0], (float)r[1], (float)r[2], (float)r[3]);
            *reinterpret_cast<float4*>(out + (size_t)E + base) =
                make_float4((float)c[0], (float)c[1], (float)c[2], (float)c[3]);
        } else {
            *reinterpret_cast<int4*>(g_r32 + base) = make_int4(r[0], r[1], r[2], r[3]);
            *reinterpret_cast<int4*>(g_c32 + base) = make_int4(c[0], c[1], c[2], c[3]);
        }
    } else {
        for (int e = base; e < E; e++) {
            int rr, cc;
            if (is64) {
                rr = (int)reinterpret_cast<const long long*>(eidx)[e];
                cc = (int)reinterpret_cast<const long long*>(eidx)[(size_t)E + e];
            } else {
                rr = reinterpret_cast<const int*>(eidx)[e];
                cc = reinterpret_cast<const int*>(eidx)[(size_t)E + e];
            }
            atomicAdd(&g_deg[cc], 1.0f);
            if (mode3) { out[e] = (float)rr; out[(size_t)E + e] = (float)cc; }
            else       { g_r32[e] = rr; g_c32[e] = cc; }
        }
    }
}

// ---------------------------------------------------------------------------
// K-C: vals[e] = (1/deg[row]) * attr[e] * diag[col]. 8 edges/thread for MLP;
// reciprocal folded in (MUFU pipe is idle in this kernel).
// ---------------------------------------------------------------------------
__global__ void val_kernel(const float* __restrict__ attr,
                           float* __restrict__ out,
                           int E, int mode3) {
    int base = (blockIdx.x * blockDim.x + threadIdx.x) * 8;
    if (base >= E) return;
    float* vo = mode3 ? (out + (size_t)2 * E) : out;

    if (base + 7 < E) {
        int r[8], c[8];
        if (mode3) {
            const float4* RF = reinterpret_cast<const float4*>(out + base);
            const float4* CF = reinterpret_cast<const float4*>(out + (size_t)E + base);
            float4 r0 = RF[0], r1 = RF[1];
            float4 c0 = CF[0], c1 = CF[1];
            r[0]=(int)r0.x; r[1]=(int)r0.y; r[2]=(int)r0.z; r[3]=(int)r0.w;
            r[4]=(int)r1.x; r[5]=(int)r1.y; r[6]=(int)r1.z; r[7]=(int)r1.w;
            c[0]=(int)c0.x; c[1]=(int)c0.y; c[2]=(int)c0.z; c[3]=(int)c0.w;
            c[4]=(int)c1.x; c[5]=(int)c1.y; c[6]=(int)c1.z; c[7]=(int)c1.w;
        } else {
            const int4* RI = reinterpret_cast<const int4*>(g_r32 + base);
            const int4* CI = reinterpret_cast<const int4*>(g_c32 + base);
            int4 r0 = RI[0], r1 = RI[1];
            int4 c0 = CI[0], c1 = CI[1];
            r[0]=r0.x; r[1]=r0.y; r[2]=r0.z; r[3]=r0.w;
            r[4]=r1.x; r[5]=r1.y; r[6]=r1.z; r[7]=r1.w;
            c[0]=c0.x; c[1]=c0.y; c[2]=c0.z; c[3]=c0.w;
            c[4]=c1.x; c[5]=c1.y; c[6]=c1.z; c[7]=c1.w;
        }

        const float4* AF = reinterpret_cast<const float4*>(attr + base);
        float4 a0 = AF[0], a1 = AF[1];
        float a[8] = {a0.x, a0.y, a0.z, a0.w, a1.x, a1.y, a1.z, a1.w};

        float dr[8], dg[8];
        #pragma unroll
        for (int k = 0; k < 8; k++) dr[k] = __ldg(&g_deg[r[k]]);
        #pragma unroll
        for (int k = 0; k < 8; k++) dg[k] = __ldg(&g_diag[c[k]]);

        float v[8];
        #pragma unroll
        for (int k = 0; k < 8; k++) v[k] = (1.0f / dr[k]) * a[k] * dg[k];

        *reinterpret_cast<float4*>(vo + base)     = make_float4(v[0], v[1], v[2], v[3]);
        *reinterpret_cast<float4*>(vo + base + 4) = make_float4(v[4], v[5], v[6], v[7]);
    } else {
        for (int e = base; e < E; e++) {
            int rr = mode3 ? (int)out[e] : g_r32[e];
            int cc = mode3 ? (int)out[(size_t)E + e] : g_c32[e];
            vo[e] = (1.0f / __ldg(&g_deg[rr])) * attr[e] * __ldg(&g_diag[cc]);
        }
    }
}

// ---------------------------------------------------------------------------
// Launch. Stream-capture fork:
//   main stream: diag
//   aux  stream: memset(g_deg) -> deg_conv
//   join -> val
// Streams/events created once on the FIRST call (the correctness run, which
// is not captured), so no resource creation happens inside capture.
// ---------------------------------------------------------------------------
extern "C" void kernel_launch(void* const* d_in, const int* in_sizes, int n_in,
                              void* d_out, int out_size) {
    const float* x    = (const float*)d_in[0];
    const void*  ei   = d_in[1];
    const float* attr = (const float*)d_in[2];
    const float* w    = (const float*)d_in[3];
    const float* b    = (const float*)d_in[4];
    float* out = (float*)d_out;

    int E = in_sizes[2];
    int N = in_sizes[0] / FEAT_D;
    int mode3 = (out_size >= 3 * E) ? 1 : 0;

    static cudaStream_t s_aux = nullptr;
    static cudaEvent_t  ev_fork = nullptr, ev_join = nullptr;
    static void* deg_addr = nullptr;
    if (s_aux == nullptr) {
        cudaStreamCreateWithFlags(&s_aux, cudaStreamNonBlocking);
        cudaEventCreateWithFlags(&ev_fork, cudaEventDisableTiming);
        cudaEventCreateWithFlags(&ev_join, cudaEventDisableTiming);
        cudaGetSymbolAddress(&deg_addr, g_deg);
    }

    // fork point on the (captured) default stream
    cudaEventRecord(ev_fork, 0);
    cudaStreamWaitEvent(s_aux, ev_fork, 0);

    // Branch B (aux): zero degrees, then degree atomics + index conversion
    cudaMemsetAsync(deg_addr, 0, (size_t)N * sizeof(float), s_aux);
    int dthreads = (E + 3) / 4;
    int dblocks  = (dthreads + 255) / 256;
    deg_conv_kernel<<<dblocks, 256, 0, s_aux>>>(ei, out, E, mode3);
    cudaEventRecord(ev_join, s_aux);

    // Branch A (main): diag
    int diag_blocks = (N + 7) / 8;
    diag_kernel<<<diag_blocks, 256>>>(x, w, b, N);

    // join, then values
    cudaStreamWaitEvent(0, ev_join, 0);
    int vthreads = (E + 7) / 8;
    int vblocks  = (vthreads + 255) / 256;
    val_kernel<<<vblocks, 256>>>(attr, out, E, mode3);
}